// round 5
// baseline (speedup 1.0000x reference)
#include <cuda_runtime.h>

#define NB 32
#define NS 8192
#define ND 64
#define NSPLIT 16
#define ROWS (NS / NSPLIT)   // 512 seq rows per CTA
#define BK 32                // rows per smem stage
#define NSTAGE (ROWS / BK)   // 16
#define BKP 36               // padded k-stride (conflict-free frags)

// Partial results: [NSPLIT][NB][3][64][64]  (mat0 = rr+ii, mat1 = ri, mat2 = ri^T)
__device__ __align__(16) float g_scratch[NSPLIT * NB * 3 * ND * ND];

__device__ __forceinline__ unsigned f2tf(float x) {
    unsigned u;
    asm("cvt.rna.tf32.f32 %0, %1;" : "=r"(u) : "f"(x));
    return u;
}

// NOT volatile: lets ptxas schedule/interleave MMAs to hide result latency.
__device__ __forceinline__ void mma_tf32(float c[4],
                                         unsigned a0, unsigned a1, unsigned a2, unsigned a3,
                                         unsigned b0, unsigned b1) {
    asm("mma.sync.aligned.m16n8k8.row.col.f32.tf32.tf32.f32 "
        "{%0,%1,%2,%3}, {%4,%5,%6,%7}, {%8,%9}, {%0,%1,%2,%3};"
        : "+f"(c[0]), "+f"(c[1]), "+f"(c[2]), "+f"(c[3])
        : "r"(a0), "r"(a1), "r"(a2), "r"(a3), "r"(b0), "r"(b1));
}

__global__ __launch_bounds__(128) void gram_kernel(const float* __restrict__ gr,
                                                   const float* __restrict__ gi) {
    // Tiles: sR/sI [2][64][BKP] transposed [d][k].  Epilogue reuses as 2x [64][65].
    __shared__ float s_raw[2 * 2 * ND * BKP];   // 9216 floats = 36 KB
    unsigned* const sRu = (unsigned*)s_raw;                 // [2][64][36]
    unsigned* const sIu = (unsigned*)s_raw + 2 * ND * BKP;  // [2][64][36]

    const int b    = blockIdx.x >> 4;           // NSPLIT = 16
    const int sp   = blockIdx.x & (NSPLIT - 1);
    const int tid  = threadIdx.x;
    const int lane = tid & 31;
    const int warp = tid >> 5;
    const int g    = lane >> 2;   // groupID
    const int t    = lane & 3;    // threadID_in_group
    const int m0   = warp * 16;   // this warp's m-band

    const float* baseR = gr + ((long)b * NS + (long)sp * ROWS) * ND;
    const float* baseI = gi + ((long)b * NS + (long)sp * ROWS) * ND;

    const int kloc = lane;        // seq row within stage
    const int dseg = warp * 16;   // 16-float d segment

    float accR[8][4];  // rr + ii accumulators, 8 n-tiles
    float accM[8][4];  // ri accumulators
#pragma unroll
    for (int j = 0; j < 8; j++)
#pragma unroll
        for (int c = 0; c < 4; c++) { accR[j][c] = 0.0f; accM[j][c] = 0.0f; }

    float4 rv[4], iv[4];

#define LOAD_STAGE(st_) do {                                      \
        const long off_ = ((long)(st_) * BK + kloc) * ND + dseg;  \
        rv[0] = *(const float4*)(baseR + off_);                   \
        rv[1] = *(const float4*)(baseR + off_ + 4);               \
        rv[2] = *(const float4*)(baseR + off_ + 8);               \
        rv[3] = *(const float4*)(baseR + off_ + 12);              \
        iv[0] = *(const float4*)(baseI + off_);                   \
        iv[1] = *(const float4*)(baseI + off_ + 4);               \
        iv[2] = *(const float4*)(baseI + off_ + 8);               \
        iv[3] = *(const float4*)(baseI + off_ + 12);              \
    } while (0)

#define STS_STAGE(buf_) do {                                          \
        unsigned* bR_ = sRu + (buf_) * ND * BKP;                      \
        unsigned* bI_ = sIu + (buf_) * ND * BKP;                      \
        const float* rf_ = (const float*)rv;                          \
        const float* if_ = (const float*)iv;                          \
        _Pragma("unroll")                                             \
        for (int c_ = 0; c_ < 16; c_++) {                             \
            bR_[(dseg + c_) * BKP + kloc] = f2tf(rf_[c_]);            \
            bI_[(dseg + c_) * BKP + kloc] = f2tf(if_[c_]);            \
        }                                                             \
    } while (0)

    // ---- prologue ----
    LOAD_STAGE(0);
    STS_STAGE(0);
    __syncthreads();

#pragma unroll 1
    for (int st = 0; st < NSTAGE; st++) {
        const int cur = st & 1;
        if (st + 1 < NSTAGE) LOAD_STAGE(st + 1);

        const unsigned* cR = sRu + cur * ND * BKP;
        const unsigned* cI = sIu + cur * ND * BKP;
#pragma unroll
        for (int kk = 0; kk < BK; kk += 8) {
            const unsigned ar0 = cR[(m0 + g    ) * BKP + kk + t    ];
            const unsigned ar1 = cR[(m0 + g + 8) * BKP + kk + t    ];
            const unsigned ar2 = cR[(m0 + g    ) * BKP + kk + t + 4];
            const unsigned ar3 = cR[(m0 + g + 8) * BKP + kk + t + 4];
            const unsigned ai0 = cI[(m0 + g    ) * BKP + kk + t    ];
            const unsigned ai1 = cI[(m0 + g + 8) * BKP + kk + t    ];
            const unsigned ai2 = cI[(m0 + g    ) * BKP + kk + t + 4];
            const unsigned ai3 = cI[(m0 + g + 8) * BKP + kk + t + 4];
            // Pass 1: rr + ri — all MMAs hit distinct accumulators (no RAW chain).
#pragma unroll
            for (int j = 0; j < 8; j++) {
                const int n0 = j * 8;
                const unsigned br0 = cR[(n0 + g) * BKP + kk + t    ];
                const unsigned br1 = cR[(n0 + g) * BKP + kk + t + 4];
                const unsigned bi0 = cI[(n0 + g) * BKP + kk + t    ];
                const unsigned bi1 = cI[(n0 + g) * BKP + kk + t + 4];
                mma_tf32(accR[j], ar0, ar1, ar2, ar3, br0, br1);  // += R^T R
                mma_tf32(accM[j], ar0, ar1, ar2, ar3, bi0, bi1);  // += R^T I
            }
            // Pass 2: ii — accR[j] reuse distance >= 8 MMA issues.
#pragma unroll
            for (int j = 0; j < 8; j++) {
                const int n0 = j * 8;
                const unsigned bi0 = cI[(n0 + g) * BKP + kk + t    ];
                const unsigned bi1 = cI[(n0 + g) * BKP + kk + t + 4];
                mma_tf32(accR[j], ai0, ai1, ai2, ai3, bi0, bi1);  // += I^T I
            }
        }

        if (st + 1 < NSTAGE) STS_STAGE((st + 1) & 1);
        __syncthreads();
    }

    // ---- epilogue: stage through smem, write 3 coalesced partial matrices ----
    // C frag map: c0:(g,2t) c1:(g,2t+1) c2:(g+8,2t) c3:(g+8,2t+1)
    float* const sA = s_raw;                 // [64][65] rr+ii
    float* const sM = s_raw + ND * 65;       // [64][65] ri
#pragma unroll
    for (int j = 0; j < 8; j++) {
        const int n  = j * 8 + 2 * t;
        const int mA = m0 + g;
        const int mB = m0 + g + 8;
        sA[mA * 65 + n]     = accR[j][0];
        sA[mA * 65 + n + 1] = accR[j][1];
        sA[mB * 65 + n]     = accR[j][2];
        sA[mB * 65 + n + 1] = accR[j][3];
        sM[mA * 65 + n]     = accM[j][0];
        sM[mA * 65 + n + 1] = accM[j][1];
        sM[mB * 65 + n]     = accM[j][2];
        sM[mB * 65 + n + 1] = accM[j][3];
    }
    __syncthreads();

    float* const base = g_scratch + ((long)(sp * NB + b) * 3 << 12);
#pragma unroll
    for (int k = 0; k < 8; k++) {
        const int idx = k * 128 + tid;     // 0..1023
        const int row = idx >> 4;
        const int col = (idx & 15) * 4;
        float4 v0, v1, v2;
        v0.x = sA[row * 65 + col];     v0.y = sA[row * 65 + col + 1];
        v0.z = sA[row * 65 + col + 2]; v0.w = sA[row * 65 + col + 3];
        v1.x = sM[row * 65 + col];     v1.y = sM[row * 65 + col + 1];
        v1.z = sM[row * 65 + col + 2]; v1.w = sM[row * 65 + col + 3];
        v2.x = sM[(col    ) * 65 + row]; v2.y = sM[(col + 1) * 65 + row];
        v2.z = sM[(col + 2) * 65 + row]; v2.w = sM[(col + 3) * 65 + row];
        *(float4*)(base +            row * ND + col) = v0;   // mat0 = rr+ii
        *(float4*)(base + 4096 +     row * ND + col) = v1;   // mat1 = ri
        *(float4*)(base + 8192 +     row * ND + col) = v2;   // mat2 = ri^T
    }
}

__global__ __launch_bounds__(256) void reduce_kernel(float* __restrict__ out) {
    const int tg  = blockIdx.x * blockDim.x + threadIdx.x;   // 65536 threads
    const int f   = tg << 2;                                 // float4 id
    const int b   = f >> 13;        // 8192 floats per batch (2 output mats)
    const int rem = f & 8191;
    const int m   = rem >> 12;      // 0 = real, 1 = imag
    const int ij  = rem & 4095;

    const float inv = 1.0f / (float)NS;
    float4 a = make_float4(0.f, 0.f, 0.f, 0.f);
    if (m == 0) {
#pragma unroll
        for (int sp = 0; sp < NSPLIT; sp++) {
            const float4 v = *(const float4*)(g_scratch +
                              ((long)((sp * NB + b) * 3) << 12) + ij);
            a.x += v.x; a.y += v.y; a.z += v.z; a.w += v.w;
        }
    } else {
#pragma unroll
        for (int sp = 0; sp < NSPLIT; sp++) {
            const float* p = g_scratch + ((long)((sp * NB + b) * 3) << 12);
            const float4 v1 = *(const float4*)(p + 4096 + ij);  // ri
            const float4 v2 = *(const float4*)(p + 8192 + ij);  // ri^T
            a.x += v1.x - v2.x; a.y += v1.y - v2.y;
            a.z += v1.z - v2.z; a.w += v1.w - v2.w;
        }
    }
    *(float4*)(out + (long)m * (NB * ND * ND) + b * (ND * ND) + ij) =
        make_float4(a.x * inv, a.y * inv, a.z * inv, a.w * inv);
}

extern "C" void kernel_launch(void* const* d_in, const int* in_sizes, int n_in,
                              void* d_out, int out_size) {
    const float* input_real = (const float*)d_in[0];
    const float* input_imag = (const float*)d_in[1];
    float* out = (float*)d_out;

    gram_kernel<<<NB * NSPLIT, 128>>>(input_real, input_imag);
    reduce_kernel<<<256, 256>>>(out);

    (void)in_sizes; (void)n_in; (void)out_size;
}

// round 6
// speedup vs baseline: 1.4101x; 1.4101x over previous
#include <cuda_runtime.h>
#include <cstdint>

#define NB 32
#define NS 8192
#define ND 64
#define NSPLIT 16
#define ROWS (NS / NSPLIT)   // 512 seq rows per CTA
#define BK 32                // rows per smem stage
#define NSTAGE (ROWS / BK)   // 16
#define DP 72                // words per k-row (64 + 8 pad): frag LDS conflict-free

// Partial results: [NSPLIT][NB][3][64][64]  (mat0 = rr+ii, mat1 = ri, mat2 = ri^T)
__device__ __align__(16) float g_scratch[NSPLIT * NB * 3 * ND * ND];

__device__ __forceinline__ unsigned f2tf(float x) {
    unsigned u;
    asm("cvt.rna.tf32.f32 %0, %1;" : "=r"(u) : "f"(x));
    return u;
}

// NOT volatile: ptxas may interleave/schedule MMAs.
__device__ __forceinline__ void mma_tf32(float c[4],
                                         unsigned a0, unsigned a1, unsigned a2, unsigned a3,
                                         unsigned b0, unsigned b1) {
    asm("mma.sync.aligned.m16n8k8.row.col.f32.tf32.tf32.f32 "
        "{%0,%1,%2,%3}, {%4,%5,%6,%7}, {%8,%9}, {%0,%1,%2,%3};"
        : "+f"(c[0]), "+f"(c[1]), "+f"(c[2]), "+f"(c[3])
        : "r"(a0), "r"(a1), "r"(a2), "r"(a3), "r"(b0), "r"(b1));
}

__global__ __launch_bounds__(256, 3) void gram_kernel(const float* __restrict__ gr,
                                                      const float* __restrict__ gi) {
    // Tiles: [2 buf][2 mat][BK][DP] tf32 = 9216 words = 36 KB.
    // Epilogue reuses first 8320 words as sA[64][65] + sM[64][65].
    __shared__ __align__(16) float s_raw[2 * 2 * BK * DP];
    unsigned* const sbase = (unsigned*)s_raw;

    const int b    = blockIdx.x >> 4;           // NSPLIT = 16
    const int sp   = blockIdx.x & (NSPLIT - 1);
    const int tid  = threadIdx.x;
    const int lane = tid & 31;
    const int warp = tid >> 5;                  // 0..7
    const int g    = lane >> 2;                 // groupID
    const int t    = lane & 3;                  // threadID_in_group
    const int m0   = (warp >> 1) * 16;          // m-band
    const int nh   = (warp & 1) * 32;           // n-half

    const float* baseR = gr + ((long)b * NS + (long)sp * ROWS) * ND;
    const float* baseI = gi + ((long)b * NS + (long)sp * ROWS) * ND;

    // Coalesced producer mapping: 8 lanes cover one 64-float row.
    const int r  = tid >> 3;          // seq row within stage (0..31)
    const int c0 = (tid & 7) * 8;     // 8-float d segment

    float accR[4][4];  // rr + ii accumulators, 4 n-tiles
    float accM[4][4];  // ri accumulators
#pragma unroll
    for (int j = 0; j < 4; j++)
#pragma unroll
        for (int c = 0; c < 4; c++) { accR[j][c] = 0.0f; accM[j][c] = 0.0f; }

    float4 rv[2], iv[2];

#define LOAD_STAGE(st_) do {                                      \
        const long off_ = ((long)(st_) * BK + r) * ND + c0;       \
        rv[0] = *(const float4*)(baseR + off_);                   \
        rv[1] = *(const float4*)(baseR + off_ + 4);               \
        iv[0] = *(const float4*)(baseI + off_);                   \
        iv[1] = *(const float4*)(baseI + off_ + 4);               \
    } while (0)

#define STS_STAGE(buf_) do {                                                   \
        unsigned* bR_ = sbase + (buf_) * 2 * BK * DP + r * DP + c0;            \
        unsigned* bI_ = bR_ + BK * DP;                                         \
        *(uint4*)(bR_)     = make_uint4(f2tf(rv[0].x), f2tf(rv[0].y),          \
                                        f2tf(rv[0].z), f2tf(rv[0].w));         \
        *(uint4*)(bR_ + 4) = make_uint4(f2tf(rv[1].x), f2tf(rv[1].y),          \
                                        f2tf(rv[1].z), f2tf(rv[1].w));         \
        *(uint4*)(bI_)     = make_uint4(f2tf(iv[0].x), f2tf(iv[0].y),          \
                                        f2tf(iv[0].z), f2tf(iv[0].w));         \
        *(uint4*)(bI_ + 4) = make_uint4(f2tf(iv[1].x), f2tf(iv[1].y),          \
                                        f2tf(iv[1].z), f2tf(iv[1].w));         \
    } while (0)

    // ---- prologue ----
    LOAD_STAGE(0);
    STS_STAGE(0);
    __syncthreads();

#pragma unroll 1
    for (int st = 0; st < NSTAGE; st++) {
        const int cur = st & 1;
        if (st + 1 < NSTAGE) LOAD_STAGE(st + 1);

        const unsigned* cR = sbase + cur * 2 * BK * DP;
        const unsigned* cI = cR + BK * DP;
#pragma unroll
        for (int kk = 0; kk < BK; kk += 8) {
            const unsigned* rA0 = cR + (kk + t) * DP;       // k = kk+t
            const unsigned* rA1 = cR + (kk + t + 4) * DP;   // k = kk+t+4
            const unsigned* rI0 = cI + (kk + t) * DP;
            const unsigned* rI1 = cI + (kk + t + 4) * DP;

            const unsigned ar0 = rA0[m0 + g];
            const unsigned ar1 = rA0[m0 + g + 8];
            const unsigned ar2 = rA1[m0 + g];
            const unsigned ar3 = rA1[m0 + g + 8];
            const unsigned ai0 = rI0[m0 + g];
            const unsigned ai1 = rI0[m0 + g + 8];
            const unsigned ai2 = rI1[m0 + g];
            const unsigned ai3 = rI1[m0 + g + 8];
            // Pass 1: rr + ri — distinct accumulators, no RAW chain.
#pragma unroll
            for (int j = 0; j < 4; j++) {
                const int n = nh + j * 8 + g;
                const unsigned br0 = rA0[n];
                const unsigned br1 = rA1[n];
                const unsigned bi0 = rI0[n];
                const unsigned bi1 = rI1[n];
                mma_tf32(accR[j], ar0, ar1, ar2, ar3, br0, br1);  // += R^T R
                mma_tf32(accM[j], ar0, ar1, ar2, ar3, bi0, bi1);  // += R^T I
            }
            // Pass 2: ii — accR[j] reuse distance >= 4 MMA issues.
#pragma unroll
            for (int j = 0; j < 4; j++) {
                const int n = nh + j * 8 + g;
                const unsigned bi0 = rI0[n];
                const unsigned bi1 = rI1[n];
                mma_tf32(accR[j], ai0, ai1, ai2, ai3, bi0, bi1);  // += I^T I
            }
        }

        if (st + 1 < NSTAGE) STS_STAGE((st + 1) & 1);
        __syncthreads();
    }

    // ---- epilogue: stage through smem, write 3 coalesced partial matrices ----
    // C frag map: c0:(g,2t) c1:(g,2t+1) c2:(g+8,2t) c3:(g+8,2t+1)
    float* const sA = s_raw;             // [64][65] rr+ii
    float* const sM = s_raw + ND * 65;   // [64][65] ri
#pragma unroll
    for (int j = 0; j < 4; j++) {
        const int n  = nh + j * 8 + 2 * t;
        const int mA = m0 + g;
        const int mB = m0 + g + 8;
        sA[mA * 65 + n]     = accR[j][0];
        sA[mA * 65 + n + 1] = accR[j][1];
        sA[mB * 65 + n]     = accR[j][2];
        sA[mB * 65 + n + 1] = accR[j][3];
        sM[mA * 65 + n]     = accM[j][0];
        sM[mA * 65 + n + 1] = accM[j][1];
        sM[mB * 65 + n]     = accM[j][2];
        sM[mB * 65 + n + 1] = accM[j][3];
    }
    __syncthreads();

    float* const base = g_scratch + ((long)(sp * NB + b) * 3 << 12);
#pragma unroll
    for (int k = 0; k < 4; k++) {
        const int idx = k * 256 + tid;     // 0..1023
        const int row = idx >> 4;
        const int col = (idx & 15) * 4;
        float4 v0, v1, v2;
        v0.x = sA[row * 65 + col];     v0.y = sA[row * 65 + col + 1];
        v0.z = sA[row * 65 + col + 2]; v0.w = sA[row * 65 + col + 3];
        v1.x = sM[row * 65 + col];     v1.y = sM[row * 65 + col + 1];
        v1.z = sM[row * 65 + col + 2]; v1.w = sM[row * 65 + col + 3];
        v2.x = sM[(col    ) * 65 + row]; v2.y = sM[(col + 1) * 65 + row];
        v2.z = sM[(col + 2) * 65 + row]; v2.w = sM[(col + 3) * 65 + row];
        *(float4*)(base +        row * ND + col) = v0;   // mat0 = rr+ii
        *(float4*)(base + 4096 + row * ND + col) = v1;   // mat1 = ri
        *(float4*)(base + 8192 + row * ND + col) = v2;   // mat2 = ri^T
    }
}

__global__ __launch_bounds__(256) void reduce_kernel(float* __restrict__ out) {
    const int tg  = blockIdx.x * blockDim.x + threadIdx.x;   // 131072 threads
    const int f   = tg << 1;                                 // float2 id
    const int b   = f >> 13;        // 8192 floats per batch (2 output mats)
    const int rem = f & 8191;
    const int m   = rem >> 12;      // 0 = real, 1 = imag
    const int ij  = rem & 4095;

    const float inv = 1.0f / (float)NS;
    float2 a = make_float2(0.f, 0.f);
    if (m == 0) {
#pragma unroll
        for (int sp = 0; sp < NSPLIT; sp++) {
            const float2 v = *(const float2*)(g_scratch +
                              ((long)((sp * NB + b) * 3) << 12) + ij);
            a.x += v.x; a.y += v.y;
        }
    } else {
#pragma unroll
        for (int sp = 0; sp < NSPLIT; sp++) {
            const float* p = g_scratch + ((long)((sp * NB + b) * 3) << 12);
            const float2 v1 = *(const float2*)(p + 4096 + ij);  // ri
            const float2 v2 = *(const float2*)(p + 8192 + ij);  // ri^T
            a.x += v1.x - v2.x; a.y += v1.y - v2.y;
        }
    }
    *(float2*)(out + (long)m * (NB * ND * ND) + b * (ND * ND) + ij) =
        make_float2(a.x * inv, a.y * inv);
}

extern "C" void kernel_launch(void* const* d_in, const int* in_sizes, int n_in,
                              void* d_out, int out_size) {
    const float* input_real = (const float*)d_in[0];
    const float* input_imag = (const float*)d_in[1];
    float* out = (float*)d_out;

    gram_kernel<<<NB * NSPLIT, 256>>>(input_real, input_imag);
    reduce_kernel<<<512, 256>>>(out);

    (void)in_sizes; (void)n_in; (void)out_size;
}

// round 8
// speedup vs baseline: 1.6146x; 1.1450x over previous
#include <cuda_runtime.h>
#include <cstdint>

#define NB 32
#define NS 8192
#define ND 64
#define NSPLIT 16
#define ROWS (NS / NSPLIT)   // 512 seq rows per CTA
#define BK 32                // seq rows per smem stage
#define NSTAGE (ROWS / BK)   // 16
#define DP 72                // words per k-row (64 + 8 pad): 72%32=8 -> frag LDS conflict-free

// Partial results: [NSPLIT][NB][3][64][64]  (mat0 = rr+ii, mat1 = ri, mat2 = ri^T)
__device__ __align__(16) float g_scratch[NSPLIT * NB * 3 * ND * ND];

__device__ __forceinline__ unsigned f2tf(float x) {
    unsigned u;
    asm("cvt.rna.tf32.f32 %0, %1;" : "=r"(u) : "f"(x));
    return u;
}

// NOT volatile: ptxas may interleave/schedule MMAs.
__device__ __forceinline__ void mma_tf32(float c[4],
                                         unsigned a0, unsigned a1, unsigned a2, unsigned a3,
                                         unsigned b0, unsigned b1) {
    asm("mma.sync.aligned.m16n8k8.row.col.f32.tf32.tf32.f32 "
        "{%0,%1,%2,%3}, {%4,%5,%6,%7}, {%8,%9}, {%0,%1,%2,%3};"
        : "+f"(c[0]), "+f"(c[1]), "+f"(c[2]), "+f"(c[3])
        : "r"(a0), "r"(a1), "r"(a2), "r"(a3), "r"(b0), "r"(b1));
}

__global__ __launch_bounds__(128, 4) void gram_kernel(const float* __restrict__ gr,
                                                      const float* __restrict__ gi) {
    // [2 buf][2 mat][BK][DP] tf32 = 9216 words = 36864 B (static, < 48KB/CTA).
    // Epilogue reuses first 8320 words as sA[64][65] + sM[64][65].
    __shared__ __align__(16) float s_raw[2 * 2 * BK * DP];
    unsigned* const sw = (unsigned*)s_raw;

    const int b    = blockIdx.x >> 4;           // NSPLIT = 16
    const int sp   = blockIdx.x & (NSPLIT - 1);
    const int tid  = threadIdx.x;
    const int L    = tid & 31;
    const int warp = tid >> 5;                  // 0..3
    const int g    = L >> 2;
    const int t    = L & 3;
    const int m0w  = (warp & 1) * 32;           // warp's 32-row m block
    const int n0w  = (warp >> 1) * 32;          // warp's 32-col n block

    const float* baseR = gr + ((long)b * NS + (long)sp * ROWS) * ND;
    const float* baseI = gi + ((long)b * NS + (long)sp * ROWS) * ND;

    float accR[2][4][4];  // rr + ii
    float accM[2][4][4];  // ri
#pragma unroll
    for (int bd = 0; bd < 2; bd++)
#pragma unroll
        for (int j = 0; j < 4; j++)
#pragma unroll
            for (int c = 0; c < 4; c++) { accR[bd][j][c] = 0.f; accM[bd][j][c] = 0.f; }

    // Producer: chunk c = tid + k*128 -> k-row = c>>4, d-quad = c&15.
    // Warp spans contiguous 512B per k_ -> fully coalesced LDG.128.
    // LDG+STS back-to-back: load regs have near-zero live range (no spill).
#define LOAD_STS_STAGE(st_, buf_) do {                                         \
        float4 rv_[4], iv_[4];                                                 \
        _Pragma("unroll")                                                      \
        for (int k_ = 0; k_ < 4; k_++) {                                       \
            const int c_ = tid + k_ * 128;                                     \
            const long o_ = ((long)(st_) * BK + (c_ >> 4)) * ND + (c_ & 15) * 4; \
            rv_[k_] = *(const float4*)(baseR + o_);                            \
            iv_[k_] = *(const float4*)(baseI + o_);                            \
        }                                                                      \
        unsigned* bp_ = sw + (buf_) * 2 * BK * DP;                             \
        _Pragma("unroll")                                                      \
        for (int k_ = 0; k_ < 4; k_++) {                                       \
            const int c_ = tid + k_ * 128;                                     \
            const int w_ = (c_ >> 4) * DP + (c_ & 15) * 4;                     \
            *(uint4*)(bp_ + w_) = make_uint4(f2tf(rv_[k_].x), f2tf(rv_[k_].y), \
                                             f2tf(rv_[k_].z), f2tf(rv_[k_].w)); \
            *(uint4*)(bp_ + BK * DP + w_) =                                    \
                make_uint4(f2tf(iv_[k_].x), f2tf(iv_[k_].y),                   \
                           f2tf(iv_[k_].z), f2tf(iv_[k_].w));                  \
        }                                                                      \
    } while (0)

    // ---- prologue ----
    LOAD_STS_STAGE(0, 0);
    __syncthreads();

#pragma unroll 1
    for (int st = 0; st < NSTAGE; st++) {
        const int cur = st & 1;
        // Producer for next stage FIRST (writes buffer last read at stage st-1,
        // protected by the previous __syncthreads).
        if (st + 1 < NSTAGE) LOAD_STS_STAGE(st + 1, (st + 1) & 1);

        const unsigned* cR = sw + cur * 2 * BK * DP;
        const unsigned* cI = cR + BK * DP;
#pragma unroll
        for (int kk = 0; kk < BK; kk += 8) {
            const unsigned* r0 = cR + (kk + t) * DP;       // k = kk+t
            const unsigned* r1 = cR + (kk + t + 4) * DP;   // k = kk+t+4
            const unsigned* i0 = cI + (kk + t) * DP;
            const unsigned* i1 = cI + (kk + t + 4) * DP;

            // A fragments: rows m0w + 16*bd + {g, g+8}
            unsigned aR[2][4], aI[2][4];
#pragma unroll
            for (int bd = 0; bd < 2; bd++) {
                const int m = m0w + 16 * bd + g;
                aR[bd][0] = r0[m];     aR[bd][1] = r0[m + 8];
                aR[bd][2] = r1[m];     aR[bd][3] = r1[m + 8];
                aI[bd][0] = i0[m];     aI[bd][1] = i0[m + 8];
                aI[bd][2] = i1[m];     aI[bd][3] = i1[m + 8];
            }
            // B fragments: shared across both bd halves.
            unsigned br0[4], br1[4], bi0[4], bi1[4];
#pragma unroll
            for (int j = 0; j < 4; j++) {
                const int n = n0w + j * 8 + g;
                br0[j] = r0[n];  br1[j] = r1[n];
                bi0[j] = i0[n];  bi1[j] = i1[n];
            }
            // Pass 1: rr + ri — 16 MMAs, all distinct accumulators.
#pragma unroll
            for (int bd = 0; bd < 2; bd++)
#pragma unroll
                for (int j = 0; j < 4; j++) {
                    mma_tf32(accR[bd][j], aR[bd][0], aR[bd][1], aR[bd][2], aR[bd][3],
                             br0[j], br1[j]);
                    mma_tf32(accM[bd][j], aR[bd][0], aR[bd][1], aR[bd][2], aR[bd][3],
                             bi0[j], bi1[j]);
                }
            // Pass 2: ii — accR reuse distance >= 8 MMA issues.
#pragma unroll
            for (int bd = 0; bd < 2; bd++)
#pragma unroll
                for (int j = 0; j < 4; j++)
                    mma_tf32(accR[bd][j], aI[bd][0], aI[bd][1], aI[bd][2], aI[bd][3],
                             bi0[j], bi1[j]);
        }
        __syncthreads();
    }

    // ---- epilogue: stage through smem, write 3 coalesced partial matrices ----
    // C frag map: c0:(r,2t) c1:(r,2t+1) c2:(r+8,2t) c3:(r+8,2t+1)
    float* const sA = s_raw;             // [64][65] rr+ii
    float* const sM = s_raw + ND * 65;   // [64][65] ri
#pragma unroll
    for (int bd = 0; bd < 2; bd++)
#pragma unroll
        for (int j = 0; j < 4; j++) {
            const int r0 = m0w + bd * 16 + g;
            const int r1 = r0 + 8;
            const int n  = n0w + j * 8 + 2 * t;
            sA[r0 * 65 + n]     = accR[bd][j][0];
            sA[r0 * 65 + n + 1] = accR[bd][j][1];
            sA[r1 * 65 + n]     = accR[bd][j][2];
            sA[r1 * 65 + n + 1] = accR[bd][j][3];
            sM[r0 * 65 + n]     = accM[bd][j][0];
            sM[r0 * 65 + n + 1] = accM[bd][j][1];
            sM[r1 * 65 + n]     = accM[bd][j][2];
            sM[r1 * 65 + n + 1] = accM[bd][j][3];
        }
    __syncthreads();

    float* const base = g_scratch + ((long)(sp * NB + b) * 3 << 12);
#pragma unroll
    for (int it = 0; it < 8; it++) {
        const int idx = it * 128 + tid;    // 0..1023
        const int row = idx >> 4;
        const int col = (idx & 15) * 4;
        float4 v0, v1, v2;
        v0.x = sA[row * 65 + col];     v0.y = sA[row * 65 + col + 1];
        v0.z = sA[row * 65 + col + 2]; v0.w = sA[row * 65 + col + 3];
        v1.x = sM[row * 65 + col];     v1.y = sM[row * 65 + col + 1];
        v1.z = sM[row * 65 + col + 2]; v1.w = sM[row * 65 + col + 3];
        v2.x = sM[(col    ) * 65 + row]; v2.y = sM[(col + 1) * 65 + row];
        v2.z = sM[(col + 2) * 65 + row]; v2.w = sM[(col + 3) * 65 + row];
        *(float4*)(base +        row * ND + col) = v0;   // mat0 = rr+ii
        *(float4*)(base + 4096 + row * ND + col) = v1;   // mat1 = ri
        *(float4*)(base + 8192 + row * ND + col) = v2;   // mat2 = ri^T
    }
}

__global__ __launch_bounds__(256) void reduce_kernel(float* __restrict__ out) {
    const int tg  = blockIdx.x * blockDim.x + threadIdx.x;   // 131072 threads
    const int f   = tg << 1;                                 // float2 id
    const int b   = f >> 13;        // 8192 floats per batch (2 output mats)
    const int rem = f & 8191;
    const int m   = rem >> 12;      // 0 = real, 1 = imag
    const int ij  = rem & 4095;

    const float inv = 1.0f / (float)NS;
    float2 a = make_float2(0.f, 0.f);
    if (m == 0) {
#pragma unroll
        for (int sp = 0; sp < NSPLIT; sp++) {
            const float2 v = *(const float2*)(g_scratch +
                              ((long)((sp * NB + b) * 3) << 12) + ij);
            a.x += v.x; a.y += v.y;
        }
    } else {
#pragma unroll
        for (int sp = 0; sp < NSPLIT; sp++) {
            const float* p = g_scratch + ((long)((sp * NB + b) * 3) << 12);
            const float2 v1 = *(const float2*)(p + 4096 + ij);  // ri
            const float2 v2 = *(const float2*)(p + 8192 + ij);  // ri^T
            a.x += v1.x - v2.x; a.y += v1.y - v2.y;
        }
    }
    *(float2*)(out + (long)m * (NB * ND * ND) + b * (ND * ND) + ij) =
        make_float2(a.x * inv, a.y * inv);
}

extern "C" void kernel_launch(void* const* d_in, const int* in_sizes, int n_in,
                              void* d_out, int out_size) {
    const float* input_real = (const float*)d_in[0];
    const float* input_imag = (const float*)d_in[1];
    float* out = (float*)d_out;

    gram_kernel<<<NB * NSPLIT, 128>>>(input_real, input_imag);
    reduce_kernel<<<512, 256>>>(out);

    (void)in_sizes; (void)n_in; (void)out_size;
}

// round 9
// speedup vs baseline: 1.6421x; 1.0170x over previous
#include <cuda_runtime.h>
#include <cstdint>

#define NB 32
#define NS 8192
#define ND 64
#define NSPLIT 16
#define ROWS (NS / NSPLIT)   // 512 seq rows per CTA
#define BK 32                // seq rows per smem stage
#define NSTAGE (ROWS / BK)   // 16
#define DP 72                // words per k-row (64 + 8 pad): frag LDS conflict-free

// Partial results: [NSPLIT][NB][3][64][64]  (mat0 = rr+ii, mat1 = ri, mat2 = ri^T)
__device__ __align__(16) float g_scratch[NSPLIT * NB * 3 * ND * ND];

__device__ __forceinline__ unsigned f2tf(float x) {
    unsigned u;
    asm("cvt.rna.tf32.f32 %0, %1;" : "=r"(u) : "f"(x));
    return u;
}

// NOT volatile: ptxas may interleave/schedule MMAs.
__device__ __forceinline__ void mma_tf32(float c[4],
                                         unsigned a0, unsigned a1, unsigned a2, unsigned a3,
                                         unsigned b0, unsigned b1) {
    asm("mma.sync.aligned.m16n8k8.row.col.f32.tf32.tf32.f32 "
        "{%0,%1,%2,%3}, {%4,%5,%6,%7}, {%8,%9}, {%0,%1,%2,%3};"
        : "+f"(c[0]), "+f"(c[1]), "+f"(c[2]), "+f"(c[3])
        : "r"(a0), "r"(a1), "r"(a2), "r"(a3), "r"(b0), "r"(b1));
}

__global__ __launch_bounds__(128, 4) void gram_kernel(const float* __restrict__ gr,
                                                      const float* __restrict__ gi) {
    // [2 buf][2 mat][BK][DP] tf32 = 9216 words = 36864 B.
    // Epilogue reuses first 8320 words as sA[64][65] + sM[64][65].
    __shared__ __align__(16) float s_raw[2 * 2 * BK * DP];
    unsigned* const sw = (unsigned*)s_raw;

    const int b    = blockIdx.x >> 4;           // NSPLIT = 16
    const int sp   = blockIdx.x & (NSPLIT - 1);
    const int tid  = threadIdx.x;
    const int L    = tid & 31;
    const int warp = tid >> 5;                  // 0..3
    const int g    = L >> 2;
    const int t    = L & 3;
    const int m0w  = (warp & 1) * 32;           // warp's 32-row m block
    const int n0w  = (warp >> 1) * 32;          // warp's 32-col n block

    const float* baseR = gr + ((long)b * NS + (long)sp * ROWS) * ND;
    const float* baseI = gi + ((long)b * NS + (long)sp * ROWS) * ND;

    float accR[2][4][4];  // rr + ii
    float accM[2][4][4];  // ri
#pragma unroll
    for (int bd = 0; bd < 2; bd++)
#pragma unroll
        for (int j = 0; j < 4; j++)
#pragma unroll
            for (int c = 0; c < 4; c++) { accR[bd][j][c] = 0.f; accM[bd][j][c] = 0.f; }

    // Producer chunk regs (half a stage: 16 regs live across <= 2 k8-steps).
    float4 rv0, rv1, iv0, iv1;

    // chunk h covers k_ in {2h, 2h+1}: c = tid + k_*128 -> k-row c>>4, d-quad c&15.
#define LOADC(st_, h_) do {                                                    \
        const int cA_ = tid + (2 * (h_)) * 128;                                \
        const int cB_ = cA_ + 128;                                             \
        const long oA_ = ((long)(st_) * BK + (cA_ >> 4)) * ND + (cA_ & 15) * 4; \
        const long oB_ = ((long)(st_) * BK + (cB_ >> 4)) * ND + (cB_ & 15) * 4; \
        rv0 = *(const float4*)(baseR + oA_);                                   \
        rv1 = *(const float4*)(baseR + oB_);                                   \
        iv0 = *(const float4*)(baseI + oA_);                                   \
        iv1 = *(const float4*)(baseI + oB_);                                   \
    } while (0)

#define STSC(buf_, h_) do {                                                    \
        unsigned* bp_ = sw + (buf_) * 2 * BK * DP;                             \
        const int cA_ = tid + (2 * (h_)) * 128;                                \
        const int cB_ = cA_ + 128;                                             \
        const int wA_ = (cA_ >> 4) * DP + (cA_ & 15) * 4;                      \
        const int wB_ = (cB_ >> 4) * DP + (cB_ & 15) * 4;                      \
        *(uint4*)(bp_ + wA_) = make_uint4(f2tf(rv0.x), f2tf(rv0.y),            \
                                          f2tf(rv0.z), f2tf(rv0.w));           \
        *(uint4*)(bp_ + wB_) = make_uint4(f2tf(rv1.x), f2tf(rv1.y),            \
                                          f2tf(rv1.z), f2tf(rv1.w));           \
        *(uint4*)(bp_ + BK * DP + wA_) = make_uint4(f2tf(iv0.x), f2tf(iv0.y),  \
                                                    f2tf(iv0.z), f2tf(iv0.w)); \
        *(uint4*)(bp_ + BK * DP + wB_) = make_uint4(f2tf(iv1.x), f2tf(iv1.y),  \
                                                    f2tf(iv1.z), f2tf(iv1.w)); \
    } while (0)

    // One k8-step of MMAs against buffer pointers cR_/cI_.
#define COMP(cR_, cI_, kk_) do {                                               \
        const unsigned* r0_ = (cR_) + ((kk_) + t) * DP;                        \
        const unsigned* r1_ = (cR_) + ((kk_) + t + 4) * DP;                    \
        const unsigned* i0_ = (cI_) + ((kk_) + t) * DP;                        \
        const unsigned* i1_ = (cI_) + ((kk_) + t + 4) * DP;                    \
        unsigned aR_[2][4], aI_[2][4];                                         \
        _Pragma("unroll")                                                      \
        for (int bd_ = 0; bd_ < 2; bd_++) {                                    \
            const int m_ = m0w + 16 * bd_ + g;                                 \
            aR_[bd_][0] = r0_[m_];     aR_[bd_][1] = r0_[m_ + 8];              \
            aR_[bd_][2] = r1_[m_];     aR_[bd_][3] = r1_[m_ + 8];              \
            aI_[bd_][0] = i0_[m_];     aI_[bd_][1] = i0_[m_ + 8];              \
            aI_[bd_][2] = i1_[m_];     aI_[bd_][3] = i1_[m_ + 8];              \
        }                                                                      \
        unsigned br0_[4], br1_[4], bi0_[4], bi1_[4];                           \
        _Pragma("unroll")                                                      \
        for (int j_ = 0; j_ < 4; j_++) {                                       \
            const int n_ = n0w + j_ * 8 + g;                                   \
            br0_[j_] = r0_[n_];  br1_[j_] = r1_[n_];                           \
            bi0_[j_] = i0_[n_];  bi1_[j_] = i1_[n_];                           \
        }                                                                      \
        _Pragma("unroll")                                                      \
        for (int bd_ = 0; bd_ < 2; bd_++)                                      \
            _Pragma("unroll")                                                  \
            for (int j_ = 0; j_ < 4; j_++) {                                   \
                mma_tf32(accR[bd_][j_], aR_[bd_][0], aR_[bd_][1],              \
                         aR_[bd_][2], aR_[bd_][3], br0_[j_], br1_[j_]);        \
                mma_tf32(accM[bd_][j_], aR_[bd_][0], aR_[bd_][1],              \
                         aR_[bd_][2], aR_[bd_][3], bi0_[j_], bi1_[j_]);        \
            }                                                                  \
        _Pragma("unroll")                                                      \
        for (int bd_ = 0; bd_ < 2; bd_++)                                      \
            _Pragma("unroll")                                                  \
            for (int j_ = 0; j_ < 4; j_++)                                     \
                mma_tf32(accR[bd_][j_], aI_[bd_][0], aI_[bd_][1],              \
                         aI_[bd_][2], aI_[bd_][3], bi0_[j_], bi1_[j_]);        \
    } while (0)

    // ---- prologue: stage 0 into buffer 0 ----
    LOADC(0, 0); STSC(0, 0);
    LOADC(0, 1); STSC(0, 1);
    __syncthreads();

#pragma unroll 1
    for (int st = 0; st < NSTAGE; st++) {
        const int cur = st & 1;
        const int nxt = cur ^ 1;
        const bool more = (st + 1 < NSTAGE);
        const unsigned* cR = sw + cur * 2 * BK * DP;
        const unsigned* cI = cR + BK * DP;

        if (more) LOADC(st + 1, 0);       // LDG chunk A: ~2 k8-steps to land
        COMP(cR, cI, 0);
        COMP(cR, cI, 8);
        if (more) { STSC(nxt, 0); LOADC(st + 1, 1); }
        COMP(cR, cI, 16);
        COMP(cR, cI, 24);
        if (more) STSC(nxt, 1);
        __syncthreads();
    }

    // ---- epilogue: stage through smem, write 3 coalesced partial matrices ----
    // C frag map: c0:(r,2t) c1:(r,2t+1) c2:(r+8,2t) c3:(r+8,2t+1)
    float* const sA = s_raw;             // [64][65] rr+ii
    float* const sM = s_raw + ND * 65;   // [64][65] ri
#pragma unroll
    for (int bd = 0; bd < 2; bd++)
#pragma unroll
        for (int j = 0; j < 4; j++) {
            const int r0 = m0w + bd * 16 + g;
            const int r1 = r0 + 8;
            const int n  = n0w + j * 8 + 2 * t;
            sA[r0 * 65 + n]     = accR[bd][j][0];
            sA[r0 * 65 + n + 1] = accR[bd][j][1];
            sA[r1 * 65 + n]     = accR[bd][j][2];
            sA[r1 * 65 + n + 1] = accR[bd][j][3];
            sM[r0 * 65 + n]     = accM[bd][j][0];
            sM[r0 * 65 + n + 1] = accM[bd][j][1];
            sM[r1 * 65 + n]     = accM[bd][j][2];
            sM[r1 * 65 + n + 1] = accM[bd][j][3];
        }
    __syncthreads();

    float* const base = g_scratch + ((long)(sp * NB + b) * 3 << 12);
#pragma unroll
    for (int it = 0; it < 8; it++) {
        const int idx = it * 128 + tid;    // 0..1023
        const int row = idx >> 4;
        const int col = (idx & 15) * 4;
        float4 v0, v1, v2;
        v0.x = sA[row * 65 + col];     v0.y = sA[row * 65 + col + 1];
        v0.z = sA[row * 65 + col + 2]; v0.w = sA[row * 65 + col + 3];
        v1.x = sM[row * 65 + col];     v1.y = sM[row * 65 + col + 1];
        v1.z = sM[row * 65 + col + 2]; v1.w = sM[row * 65 + col + 3];
        v2.x = sM[(col    ) * 65 + row]; v2.y = sM[(col + 1) * 65 + row];
        v2.z = sM[(col + 2) * 65 + row]; v2.w = sM[(col + 3) * 65 + row];
        *(float4*)(base +        row * ND + col) = v0;   // mat0 = rr+ii
        *(float4*)(base + 4096 + row * ND + col) = v1;   // mat1 = ri
        *(float4*)(base + 8192 + row * ND + col) = v2;   // mat2 = ri^T
    }
}

__global__ __launch_bounds__(256) void reduce_kernel(float* __restrict__ out) {
    // One float per thread: 262144 threads. m is block-uniform (4096-float regions).
    const int f   = blockIdx.x * blockDim.x + threadIdx.x;
    const int b   = f >> 13;        // 8192 floats per batch (2 output mats)
    const int rem = f & 8191;
    const int m   = rem >> 12;      // 0 = real, 1 = imag (uniform per block)
    const int ij  = rem & 4095;

    const float inv = 1.0f / (float)NS;
    float a = 0.f;
    if (m == 0) {
#pragma unroll
        for (int sp = 0; sp < NSPLIT; sp++)
            a += g_scratch[(((long)(sp * NB + b) * 3) << 12) + ij];
    } else {
#pragma unroll
        for (int sp = 0; sp < NSPLIT; sp++) {
            const float* p = g_scratch + (((long)(sp * NB + b) * 3) << 12);
            a += p[4096 + ij] - p[8192 + ij];   // ri - ri^T
        }
    }
    out[(long)m * (NB * ND * ND) + b * (ND * ND) + ij] = a * inv;
}

extern "C" void kernel_launch(void* const* d_in, const int* in_sizes, int n_in,
                              void* d_out, int out_size) {
    const float* input_real = (const float*)d_in[0];
    const float* input_imag = (const float*)d_in[1];
    float* out = (float*)d_out;

    gram_kernel<<<NB * NSPLIT, 128>>>(input_real, input_imag);
    reduce_kernel<<<1024, 256>>>(out);

    (void)in_sizes; (void)n_in; (void)out_size;
}

// round 10
// speedup vs baseline: 2.1287x; 1.2963x over previous
#include <cuda_runtime.h>
#include <cuda_fp16.h>
#include <cstdint>

#define NB 32
#define NS 8192
#define ND 64
#define NSPLIT 16
#define ROWS (NS / NSPLIT)   // 512 seq rows per CTA
#define BK 32                // seq rows per smem stage
#define NSTAGE (ROWS / BK)   // 16
#define KP 16                // half2 k-pair rows per stage
#define DP2 72               // words per kpair row (64 + 8 pad): 72%32=8 -> CF LDS
#define MATW (KP * DP2)      // 1152 words per matrix per buffer

// Partial results: [NSPLIT][NB][3][64][64]  (mat0 = rr+ii, mat1 = ri, mat2 = ri^T)
__device__ __align__(16) float g_scratch[NSPLIT * NB * 3 * ND * ND];

// Pack two floats into f16x2: lo -> low half (smaller k), hi -> high half.
__device__ __forceinline__ unsigned pk(float lo, float hi) {
    unsigned u;
    asm("cvt.rn.f16x2.f32 %0, %1, %2;" : "=r"(u) : "f"(hi), "f"(lo));
    return u;
}

// NOT volatile: ptxas may interleave/schedule MMAs. K=16 per instruction.
__device__ __forceinline__ void mma_f16(float c[4],
                                        unsigned a0, unsigned a1, unsigned a2, unsigned a3,
                                        unsigned b0, unsigned b1) {
    asm("mma.sync.aligned.m16n8k16.row.col.f32.f16.f16.f32 "
        "{%0,%1,%2,%3}, {%4,%5,%6,%7}, {%8,%9}, {%0,%1,%2,%3};"
        : "+f"(c[0]), "+f"(c[1]), "+f"(c[2]), "+f"(c[3])
        : "r"(a0), "r"(a1), "r"(a2), "r"(a3), "r"(b0), "r"(b1));
}

__global__ __launch_bounds__(128, 4) void gram_kernel(const float* __restrict__ gr,
                                                      const float* __restrict__ gi) {
    // Main loop: [2 buf][2 mat][KP][DP2] u32 = 4608 words (18.4 KB).
    // Epilogue reuses as sA[64][65] + sM[64][65] = 8320 floats -> size for that.
    __shared__ __align__(16) float s_raw[8320];
    unsigned* const sw = (unsigned*)s_raw;

    const int b    = blockIdx.x >> 4;           // NSPLIT = 16
    const int sp   = blockIdx.x & (NSPLIT - 1);
    const int tid  = threadIdx.x;
    const int L    = tid & 31;
    const int warp = tid >> 5;                  // 0..3
    const int g    = L >> 2;
    const int t    = L & 3;
    const int m0w  = (warp & 1) * 32;           // warp's 32-row m block
    const int n0w  = (warp >> 1) * 32;          // warp's 32-col n block

    const float* baseR = gr + ((long)b * NS + (long)sp * ROWS) * ND;
    const float* baseI = gi + ((long)b * NS + (long)sp * ROWS) * ND;

    float accR[2][4][4];  // rr + ii
    float accM[2][4][4];  // ri
#pragma unroll
    for (int bd = 0; bd < 2; bd++)
#pragma unroll
        for (int j = 0; j < 4; j++)
#pragma unroll
            for (int c = 0; c < 4; c++) { accR[bd][j][c] = 0.f; accM[bd][j][c] = 0.f; }

    // Producer unit u = tid + h*128: kpair p = u>>4 (0..15), d-quad q = u&15.
    // Loads k-rows 2p and 2p+1 at d = 4q..4q+3 for both matrices (coalesced:
    // 16 consecutive tids cover one 256B row segment).
    float4 rv0, rv1, iv0, iv1;   // chunk regs: rows 2p (rv0/iv0), 2p+1 (rv1/iv1)

#define LOADC(st_, h_) do {                                                    \
        const int u_ = tid + (h_) * 128;                                       \
        const int p_ = u_ >> 4, q_ = u_ & 15;                                  \
        const long oA_ = ((long)(st_) * BK + 2 * p_) * ND + 4 * q_;            \
        rv0 = *(const float4*)(baseR + oA_);                                   \
        rv1 = *(const float4*)(baseR + oA_ + ND);                              \
        iv0 = *(const float4*)(baseI + oA_);                                   \
        iv1 = *(const float4*)(baseI + oA_ + ND);                              \
    } while (0)

#define STSC(buf_, h_) do {                                                    \
        const int u_ = tid + (h_) * 128;                                       \
        const int p_ = u_ >> 4, q_ = u_ & 15;                                  \
        unsigned* bp_ = sw + (buf_) * 2 * MATW + p_ * DP2 + 4 * q_;            \
        *(uint4*)bp_ = make_uint4(pk(rv0.x, rv1.x), pk(rv0.y, rv1.y),          \
                                  pk(rv0.z, rv1.z), pk(rv0.w, rv1.w));         \
        *(uint4*)(bp_ + MATW) = make_uint4(pk(iv0.x, iv1.x), pk(iv0.y, iv1.y), \
                                           pk(iv0.z, iv1.z), pk(iv0.w, iv1.w)); \
    } while (0)

    // One k16-step: fragment LDS (bank = 8t+g+c, conflict-free) + 24 MMAs.
#define COMP(cR_, cI_, s_) do {                                                \
        const int kb_ = 8 * (s_);                                              \
        const unsigned* pr0_ = (cR_) + (kb_ + t) * DP2;                        \
        const unsigned* pr1_ = (cR_) + (kb_ + t + 4) * DP2;                    \
        const unsigned* pi0_ = (cI_) + (kb_ + t) * DP2;                        \
        const unsigned* pi1_ = (cI_) + (kb_ + t + 4) * DP2;                    \
        unsigned aR_[2][4], aI_[2][4];                                         \
        _Pragma("unroll")                                                      \
        for (int bd_ = 0; bd_ < 2; bd_++) {                                    \
            const int m_ = m0w + 16 * bd_ + g;                                 \
            aR_[bd_][0] = pr0_[m_];  aR_[bd_][1] = pr0_[m_ + 8];               \
            aR_[bd_][2] = pr1_[m_];  aR_[bd_][3] = pr1_[m_ + 8];               \
            aI_[bd_][0] = pi0_[m_];  aI_[bd_][1] = pi0_[m_ + 8];               \
            aI_[bd_][2] = pi1_[m_];  aI_[bd_][3] = pi1_[m_ + 8];               \
        }                                                                      \
        unsigned br0_[4], br1_[4], bi0_[4], bi1_[4];                           \
        _Pragma("unroll")                                                      \
        for (int j_ = 0; j_ < 4; j_++) {                                       \
            const int n_ = n0w + j_ * 8 + g;                                   \
            br0_[j_] = pr0_[n_];  br1_[j_] = pr1_[n_];                         \
            bi0_[j_] = pi0_[n_];  bi1_[j_] = pi1_[n_];                         \
        }                                                                      \
        _Pragma("unroll")                                                      \
        for (int bd_ = 0; bd_ < 2; bd_++)                                      \
            _Pragma("unroll")                                                  \
            for (int j_ = 0; j_ < 4; j_++) {                                   \
                mma_f16(accR[bd_][j_], aR_[bd_][0], aR_[bd_][1],               \
                        aR_[bd_][2], aR_[bd_][3], br0_[j_], br1_[j_]);         \
                mma_f16(accM[bd_][j_], aR_[bd_][0], aR_[bd_][1],               \
                        aR_[bd_][2], aR_[bd_][3], bi0_[j_], bi1_[j_]);         \
            }                                                                  \
        _Pragma("unroll")                                                      \
        for (int bd_ = 0; bd_ < 2; bd_++)                                      \
            _Pragma("unroll")                                                  \
            for (int j_ = 0; j_ < 4; j_++)                                     \
                mma_f16(accR[bd_][j_], aI_[bd_][0], aI_[bd_][1],               \
                        aI_[bd_][2], aI_[bd_][3], bi0_[j_], bi1_[j_]);         \
    } while (0)

    // ---- prologue: stage 0 into buffer 0 ----
    LOADC(0, 0); STSC(0, 0);
    LOADC(0, 1); STSC(0, 1);
    __syncthreads();

#pragma unroll 1
    for (int st = 0; st < NSTAGE; st++) {
        const int cur = st & 1;
        const int nxt = cur ^ 1;
        const bool more = (st + 1 < NSTAGE);
        const unsigned* cR = sw + cur * 2 * MATW;
        const unsigned* cI = cR + MATW;

        if (more) LOADC(st + 1, 0);
        COMP(cR, cI, 0);
        if (more) { STSC(nxt, 0); LOADC(st + 1, 1); }
        COMP(cR, cI, 1);
        if (more) STSC(nxt, 1);
        __syncthreads();
    }

    // ---- epilogue: stage through smem, write 3 coalesced partial matrices ----
    // C frag map: c0:(r,2t) c1:(r,2t+1) c2:(r+8,2t) c3:(r+8,2t+1)
    float* const sA = s_raw;             // [64][65] rr+ii
    float* const sM = s_raw + ND * 65;   // [64][65] ri
#pragma unroll
    for (int bd = 0; bd < 2; bd++)
#pragma unroll
        for (int j = 0; j < 4; j++) {
            const int r0 = m0w + bd * 16 + g;
            const int r1 = r0 + 8;
            const int n  = n0w + j * 8 + 2 * t;
            sA[r0 * 65 + n]     = accR[bd][j][0];
            sA[r0 * 65 + n + 1] = accR[bd][j][1];
            sA[r1 * 65 + n]     = accR[bd][j][2];
            sA[r1 * 65 + n + 1] = accR[bd][j][3];
            sM[r0 * 65 + n]     = accM[bd][j][0];
            sM[r0 * 65 + n + 1] = accM[bd][j][1];
            sM[r1 * 65 + n]     = accM[bd][j][2];
            sM[r1 * 65 + n + 1] = accM[bd][j][3];
        }
    __syncthreads();

    float* const base = g_scratch + ((long)(sp * NB + b) * 3 << 12);
#pragma unroll
    for (int it = 0; it < 8; it++) {
        const int idx = it * 128 + tid;    // 0..1023
        const int row = idx >> 4;
        const int col = (idx & 15) * 4;
        float4 v0, v1, v2;
        v0.x = sA[row * 65 + col];     v0.y = sA[row * 65 + col + 1];
        v0.z = sA[row * 65 + col + 2]; v0.w = sA[row * 65 + col + 3];
        v1.x = sM[row * 65 + col];     v1.y = sM[row * 65 + col + 1];
        v1.z = sM[row * 65 + col + 2]; v1.w = sM[row * 65 + col + 3];
        v2.x = sM[(col    ) * 65 + row]; v2.y = sM[(col + 1) * 65 + row];
        v2.z = sM[(col + 2) * 65 + row]; v2.w = sM[(col + 3) * 65 + row];
        *(float4*)(base +        row * ND + col) = v0;   // mat0 = rr+ii
        *(float4*)(base + 4096 + row * ND + col) = v1;   // mat1 = ri
        *(float4*)(base + 8192 + row * ND + col) = v2;   // mat2 = ri^T
    }
}

__global__ __launch_bounds__(256) void reduce_kernel(float* __restrict__ out) {
    // One float per thread: 262144 threads. m is block-uniform (4096-float regions).
    const int f   = blockIdx.x * blockDim.x + threadIdx.x;
    const int b   = f >> 13;        // 8192 floats per batch (2 output mats)
    const int rem = f & 8191;
    const int m   = rem >> 12;      // 0 = real, 1 = imag (uniform per block)
    const int ij  = rem & 4095;

    const float inv = 1.0f / (float)NS;
    float a = 0.f;
    if (m == 0) {
#pragma unroll
        for (int sp = 0; sp < NSPLIT; sp++)
            a += g_scratch[(((long)(sp * NB + b) * 3) << 12) + ij];
    } else {
#pragma unroll
        for (int sp = 0; sp < NSPLIT; sp++) {
            const float* p = g_scratch + (((long)(sp * NB + b) * 3) << 12);
            a += p[4096 + ij] - p[8192 + ij];   // ri - ri^T
        }
    }
    out[(long)m * (NB * ND * ND) + b * (ND * ND) + ij] = a * inv;
}

extern "C" void kernel_launch(void* const* d_in, const int* in_sizes, int n_in,
                              void* d_out, int out_size) {
    const float* input_real = (const float*)d_in[0];
    const float* input_imag = (const float*)d_in[1];
    float* out = (float*)d_out;

    gram_kernel<<<NB * NSPLIT, 128>>>(input_real, input_imag);
    reduce_kernel<<<1024, 256>>>(out);

    (void)in_sizes; (void)n_in; (void)out_size;
}